// round 11
// baseline (speedup 1.0000x reference)
#include <cuda_runtime.h>
#include <cuda_fp16.h>
#include <cstdint>
#include <cstddef>

// Problem shapes (fixed): B=64, T=512, D=512, N=1024, 4N=4096
#define BB 64
#define TT 512
#define DD 512
#define NN 1024
#define GG 4096

// ---------------------------------------------------------------------------
// Device-global scratch
// ---------------------------------------------------------------------------
__device__ float    g_xp[(size_t)TT * BB * GG];   // [T][B][4N] input projections (fp32)
__device__ __half   g_xh[(size_t)BB * TT * DD];   // x converted to fp16
__device__ __half   g_wxt[(size_t)4 * NN * DD];   // Wx gates transposed [gate][n][k] fp16
__device__ __half   g_hbuf[2][BB * NN];           // parity double-buffered h (fp16)
__device__ unsigned g_flags[128 * 8];             // per-CTA step flags, padded to 32B

// ---------------------------------------------------------------------------
// Helpers
// ---------------------------------------------------------------------------
static __device__ __forceinline__ unsigned h2u(__half2 h) { return *(unsigned*)&h; }

static __device__ __forceinline__ float sigf(float x) { return 1.0f / (1.0f + __expf(-x)); }
static __device__ __forceinline__ float tanh_fast(float x) { return 2.0f * sigf(2.0f * x) - 1.0f; }

static __device__ __forceinline__ unsigned smaddr(const void* p) {
    return (unsigned)__cvta_generic_to_shared(p);
}
#define CP16(d, s)  asm volatile("cp.async.cg.shared.global [%0], [%1], 16;" :: "r"(d), "l"(s))
#define CPCOMMIT()  asm volatile("cp.async.commit_group;")

template <int NPend>
static __device__ __forceinline__ void cpwait() {
    asm volatile("cp.async.wait_group %0;" :: "n"(NPend));
}

// ldmatrix x4: 4 8x8 b16 tiles -> 4 regs (lane l of each tile: row l>>2, pair l&3)
static __device__ __forceinline__ void ldsm4(unsigned* r, unsigned addr) {
    asm volatile("ldmatrix.sync.aligned.m8n8.x4.shared.b16 {%0,%1,%2,%3}, [%4];"
        : "=r"(r[0]), "=r"(r[1]), "=r"(r[2]), "=r"(r[3]) : "r"(addr));
}

// fp16 mma m16n8k16, fp32 accumulate (in place)
static __device__ __forceinline__ void mma16(float* d, const unsigned* a, unsigned b0, unsigned b1) {
    asm volatile(
        "mma.sync.aligned.m16n8k16.row.col.f32.f16.f16.f32 "
        "{%0,%1,%2,%3},{%4,%5,%6,%7},{%8,%9},{%0,%1,%2,%3};"
        : "+f"(d[0]), "+f"(d[1]), "+f"(d[2]), "+f"(d[3])
        : "r"(a[0]), "r"(a[1]), "r"(a[2]), "r"(a[3]), "r"(b0), "r"(b1));
}

static __device__ __forceinline__ unsigned ld_acq(const unsigned* p) {
    unsigned v;
    asm volatile("ld.global.acquire.gpu.u32 %0, [%1];" : "=r"(v) : "l"(p));
    return v;
}
static __device__ __forceinline__ void st_rel(unsigned* p, unsigned v) {
    asm volatile("st.global.release.gpu.u32 [%0], %1;" :: "l"(p), "r"(v));
}

// ---------------------------------------------------------------------------
// Init + input conversion kernels (run every replay; cheap)
// ---------------------------------------------------------------------------
__global__ void init_kernel(const float* __restrict__ h0) {
    int i = blockIdx.x * 256 + threadIdx.x;       // 65536 threads == BB*NN
    g_hbuf[0][i] = __float2half_rn(h0[i]);
    if (i < 128 * 8) g_flags[i] = 0u;
}

__global__ void conv_x_kernel(const float* __restrict__ x) {
    size_t i = (size_t)blockIdx.x * 256 + threadIdx.x;   // BB*TT*DD threads
    g_xh[i] = __float2half_rn(x[i]);
}

// g_wxt[gate][n][k] = fp16(Wgate[k][n])
__global__ void conv_w_kernel(
    const float* __restrict__ Wfx, const float* __restrict__ Wix,
    const float* __restrict__ Wox, const float* __restrict__ Wcx)
{
    size_t e = (size_t)blockIdx.x * 256 + threadIdx.x;   // 4*NN*DD threads
    int k    = (int)(e & (DD - 1));
    int n    = (int)((e >> 9) & (NN - 1));
    int gate = (int)(e >> 19);
    const float* W = (gate == 0) ? Wfx : (gate == 1) ? Wix : (gate == 2) ? Wox : Wcx;
    g_wxt[e] = __float2half_rn(W[(size_t)k * NN + n]);
}

// ---------------------------------------------------------------------------
// Phase 1: xp = x @ [Wfx|Wix|Wox|Wcx] + bias  (fp16 m16n8k16, fp32 acc)
// grid (256 m-blocks, 32 n-blocks), 256 threads, BM=BN=128, BK=32 halfs.
// Ring-4 single-sync pipeline: stage(c+2) at top of iter c, ONE syncthreads
// per chunk (slot reuse is separated by the previous iteration's barrier).
// Stride-20 rows (16 data + 4 pad words): ldsm banks {20r+4s mod 32} cover
// all 32 banks exactly once per tile -> conflict-free.
// ---------------------------------------------------------------------------
#define P1_TSTR  20                       // words per row
#define P1_TILE  (128 * P1_TSTR)          // 2560 words per tile
#define P1_SMEMB (4 * 2 * P1_TILE * 4)    // 81920 bytes (4 slots x (A+B))

__global__ void __launch_bounds__(256, 2) xproj_kernel(
    const float* __restrict__ bf, const float* __restrict__ bi,
    const float* __restrict__ bo, const float* __restrict__ bc)
{
    extern __shared__ unsigned smu[];
    unsigned* AsP = smu;                      // [4][128][20]
    unsigned* BsP = smu + 4 * P1_TILE;        // [4][128][20]

    const int tid  = threadIdx.x;
    const int warp = tid >> 5, lane = tid & 31;
    const int g    = lane >> 2, tig = lane & 3;
    const int wm   = warp >> 1, wn = warp & 1;
    const int M0   = blockIdx.x * 128;
    const int gate = blockIdx.y >> 3;
    const int nc0  = (blockIdx.y & 7) * 128;
    const __half* Wt  = g_wxt + (size_t)gate * NN * DD;
    const float* bias = (gate == 0) ? bf : (gate == 1) ? bi : (gate == 2) ? bo : bc;

    const unsigned sb = smaddr(smu);
    // A x4 tile for mf: rows wm*32+mf*16 + (lane&15), seg (lane>>4)*4 words
    const unsigned aoff = sb + (((wm * 32 + (lane & 15)) * P1_TSTR + (lane >> 4) * 4) << 2);
    // B x4 group nfp: rows wn*64+nfp*16 + (lane&7) + ((lane>>4)&1)*8, seg ((lane>>3)&1)*4
    const unsigned boff0 = sb + ((4 * P1_TILE +
                     ((wn * 64 + (lane & 7) + ((lane >> 4) & 1) * 8) * P1_TSTR +
                      ((lane >> 3) & 1) * 4)) << 2);

    float acc[2][8][4];
    #pragma unroll
    for (int a = 0; a < 2; a++)
        #pragma unroll
        for (int b = 0; b < 8; b++)
            #pragma unroll
            for (int q = 0; q < 4; q++) acc[a][b][q] = 0.0f;

    auto stage = [&](int c) {
        const int k0 = c * 32;                           // halfs
        const int slot = c & 3;
        unsigned* Ad = AsP + slot * P1_TILE;
        unsigned* Bd = BsP + slot * P1_TILE;
        #pragma unroll
        for (int i = 0; i < 2; i++) {
            int s = tid + 256 * i;                       // 0..511: 128 rows x 4 segs
            int row = s >> 2, seg = s & 3;
            CP16(smaddr(Ad + row * P1_TSTR + seg * 4),
                 g_xh + (size_t)(M0 + row) * DD + k0 + seg * 8);
            CP16(smaddr(Bd + row * P1_TSTR + seg * 4),
                 Wt + (size_t)(nc0 + row) * DD + k0 + seg * 8);
        }
        CPCOMMIT();
    };

    stage(0); stage(1);
    for (int c = 0; c < 16; c++) {
        if (c + 2 < 16) stage(c + 2);
        if (c <= 13)      cpwait<2>();
        else if (c == 14) cpwait<1>();
        else              cpwait<0>();
        __syncthreads();
        const unsigned bufB = (unsigned)((c & 3) * P1_TILE * 4);
        #pragma unroll
        for (int ks2 = 0; ks2 < 2; ks2++) {
            const unsigned kB = bufB + ks2 * 32;         // 8 words = 32 bytes
            unsigned a[2][4];
            ldsm4(a[0], aoff + kB);
            ldsm4(a[1], aoff + kB + 16 * P1_TSTR * 4);
            #pragma unroll
            for (int nfp = 0; nfp < 4; nfp++) {
                unsigned b4[4];
                ldsm4(b4, boff0 + kB + nfp * 16 * P1_TSTR * 4);
                mma16(acc[0][2 * nfp],     a[0], b4[0], b4[1]);
                mma16(acc[1][2 * nfp],     a[1], b4[0], b4[1]);
                mma16(acc[0][2 * nfp + 1], a[0], b4[2], b4[3]);
                mma16(acc[1][2 * nfp + 1], a[1], b4[2], b4[3]);
            }
        }
    }

    #pragma unroll
    for (int mf = 0; mf < 2; mf++) {
        #pragma unroll
        for (int rr = 0; rr < 2; rr++) {
            int m = M0 + wm * 32 + mf * 16 + g + rr * 8;
            int b = m >> 9, t = m & 511;
            size_t base = ((size_t)t * BB + b) * GG + (size_t)blockIdx.y * 128;
            #pragma unroll
            for (int nf = 0; nf < 8; nf++) {
                int col = wn * 64 + nf * 8 + 2 * tig;
                float v0 = acc[mf][nf][rr * 2 + 0] + bias[nc0 + col];
                float v1 = acc[mf][nf][rr * 2 + 1] + bias[nc0 + col + 1];
                *(float2*)&g_xp[base + col] = make_float2(v0, v1);
            }
        }
    }
}

// ---------------------------------------------------------------------------
// Phase 2: persistent LSTM recurrence. 128 CTAs x 256 threads (8 warps).
// fp16 h + fp16 Wh fragments, m16n8k16.
//
// 2-ROW x 4-K WARP SPLIT: warp w = (rhh = w&1, kq = w>>1) owns rows
// [32*rhh, +32) x k [256*kq, +256). 8 chunks of 32 rows x 32 k, 4-deep
// cp.async ring. 4-way cross-warp reduction (halved vs 8-way k-split).
// Per-chunk producer waits: chunk c depends on 4 CTAs [32kq+4c, +4).
// No post-mma syncwarp: ldmatrix/mma are warp-convergent, so after the
// last collective ldsm of a slot every lane holds its data -> restage safe.
// Ring-parity safety unchanged: h stored into buf[(t+1)&1] only after the
// reduction __syncthreads (all warps passed all waits; union = all 128
// CTAs at step >= t), so buf[(t-1)&1] is fully consumed before overwrite.
// ---------------------------------------------------------------------------
#define P2_WHU    16384                   // Wh fragment uints: 64 ks x 2 parts x 32 x 4
#define P2_CHW    (32 * 20)               // chunk: 32 rows x 20 words = 640 words
#define P2_RING   (4 * P2_CHW)            // 4-slot ring per warp = 2560 words
#define P2_SMEMW  (P2_WHU + 8 * P2_RING)  // 36864 words
#define P2_SMEMB  (P2_SMEMW * 4)          // 147456 bytes

__global__ void __launch_bounds__(256, 1) lstm_kernel(
    const float* __restrict__ c0,
    const float* __restrict__ Wfh, const float* __restrict__ Wih,
    const float* __restrict__ Woh, const float* __restrict__ Wch,
    const float* __restrict__ wcf, const float* __restrict__ wci,
    const float* __restrict__ wco,
    float* __restrict__ out)
{
    extern __shared__ unsigned smu[];
    unsigned* whfu = smu;                         // fill view
    const uint4* whf4 = (const uint4*)smu;        // [(ks*2+part)*32 + lane]
    unsigned* Aswbase = smu + P2_WHU;             // 8 warp rings

    const int tid  = threadIdx.x;
    const int warp = tid >> 5, lane = tid & 31;
    const int g    = lane >> 2, tig = lane & 3;
    const int cta  = blockIdx.x;
    const int n0   = cta * 8;

    const int rhh = warp & 1;                 // row half (32 rows)
    const int kq  = warp >> 1;                // k quarter (256 halfs)
    const int rowbase = rhh * 32;
    const int kbase   = kq * 256;

    unsigned* Asw = Aswbase + warp * P2_RING;

    // LDSM A-frag base (bytes) for m-tile mt: rows mt*16 + (lane&15), seg (lane>>4)*4
    const unsigned aaddr0 = smaddr(Asw) + (((lane & 15) * 20 + (lane >> 4) * 4) << 2);

    // --- Prologue: build fp16 Wh fragments in SMEM (resident for all steps)
    for (int e = tid; e < P2_WHU; e += 256) {
        int j     = e & 3;
        int lane_ = (e >> 2) & 31;
        int part  = (e >> 7) & 1;
        int ks    = e >> 8;                    // 0..63
        int gate  = part * 2 + (j >> 1);       // 0=f 1=i 2=o 3=c
        int which = j & 1;                     // b0 / b1
        int tg    = lane_ & 3;
        int col   = n0 + (lane_ >> 2);
        int kb    = ks * 16 + 2 * tg + which * 8;
        const float* Wsel = (gate == 0) ? Wfh : (gate == 1) ? Wih : (gate == 2) ? Woh : Wch;
        __half2 v = __floats2half2_rn(Wsel[(size_t)kb * NN + col],
                                      Wsel[(size_t)(kb + 1) * NN + col]);
        whfu[e] = h2u(v);
    }

    // --- Per-thread update-cell ownership: 1 row x 2 cols (same map as R10)
    const int bown = (warp >> 1) * 16 + (warp & 1) * 8 + g;
    const int nA   = n0 + 2 * tig;
    // Reduction source selectors (bits of bown)
    const int rhh_r = (warp >> 2) & 1;
    const int mt_r  = (warp >> 1) & 1;
    const int hb_r  = warp & 1;

    float2 cv2 = *(const float2*)&c0[bown * NN + nA];
    float creg[2] = {cv2.x, cv2.y};
    float2 pf2 = *(const float2*)&wcf[nA];
    float2 pi2 = *(const float2*)&wci[nA];
    float2 po2 = *(const float2*)&wco[nA];
    const float pfv[2] = {pf2.x, pf2.y};
    const float piv[2] = {pi2.x, pi2.y};
    const float pov[2] = {po2.x, po2.y};

    __syncthreads();   // whf ready

    for (int t = 0; t < TT; t++) {
        const __half* hsrc = g_hbuf[t & 1];
        __half* hdst = g_hbuf[(t + 1) & 1];

        // Prefetch xp BEFORE any wait (no h dependency)
        const float* xpt = g_xp + (size_t)t * BB * GG;
        float2 xv[4];
        #pragma unroll
        for (int nt = 0; nt < 4; nt++)
            xv[nt] = *(const float2*)&xpt[(size_t)bown * GG + nt * NN + nA];

        // Per-chunk producer wait: 4 CTAs [32kq+4c, +4) at step >= t
        auto waitkc = [&](int c) {
            if (t > 0) {
                const unsigned tgt = (unsigned)t;
                if (lane < 4) {
                    const unsigned* f = &g_flags[(32 * kq + 4 * c + lane) * 8];
                    while (ld_acq(f) < tgt) { }
                }
                __syncwarp();
            }
        };

        float acc[2][4][4] __attribute__((aligned(16)));
        #pragma unroll
        for (int a = 0; a < 2; a++)
            #pragma unroll
            for (int b = 0; b < 4; b++)
                #pragma unroll
                for (int q = 0; q < 4; q++) acc[a][b][q] = 0.0f;

        // Stage chunk c: rows rowbase..+32, k halfs kbase + c*32..+32
        auto stageh = [&](int c) {
            const __half* src = hsrc + (size_t)rowbase * NN + kbase + c * 32;
            unsigned* dst = Asw + (c & 3) * P2_CHW;
            #pragma unroll
            for (int i = 0; i < 4; i++) {
                int s = lane + 32 * i;                // 32 rows x 4 16B-segs
                int row = s >> 2, seg = s & 3;
                CP16(smaddr(dst + row * 20 + seg * 4), src + (size_t)row * NN + seg * 8);
            }
            CPCOMMIT();
        };

        waitkc(0); stageh(0);
        waitkc(1); stageh(1);
        waitkc(2); stageh(2);
        waitkc(3); stageh(3);

        #pragma unroll
        for (int c = 0; c < 8; c++) {
            if (c <= 4)      cpwait<3>();
            else if (c == 5) cpwait<2>();
            else if (c == 6) cpwait<1>();
            else             cpwait<0>();
            __syncwarp();     // cp.async visibility across lanes before collective ldsm
            const unsigned abase = aaddr0 + (unsigned)((c & 3) * P2_CHW * 4);
            #pragma unroll
            for (int ks2 = 0; ks2 < 2; ks2++) {
                const int ks = kq * 16 + c * 2 + ks2;
                const uint4 uA = whf4[(ks * 2 + 0) * 32 + lane];
                const uint4 uB = whf4[(ks * 2 + 1) * 32 + lane];
                #pragma unroll
                for (int mt = 0; mt < 2; mt++) {
                    unsigned a[4];
                    ldsm4(a, abase + (unsigned)(mt * 16 * 20 * 4) + ks2 * 32);
                    mma16(acc[mt][0], a, uA.x, uA.y);   // forget
                    mma16(acc[mt][1], a, uA.z, uA.w);   // input
                    mma16(acc[mt][2], a, uB.x, uB.y);   // output
                    mma16(acc[mt][3], a, uB.z, uB.w);   // cell
                }
            }
            // No post-mma syncwarp needed: ldsm/mma are warp-convergent.
            if (c + 4 < 8) { waitkc(c + 4); stageh(c + 4); }
        }

        // --- Cross-warp (4-way) reduction via smem (reuse own ring region)
        float* Aswf = (float*)Asw;
        #pragma unroll
        for (int mt = 0; mt < 2; mt++)
            #pragma unroll
            for (int gt = 0; gt < 4; gt++)
                *(float4*)&Aswf[((mt * 4 + gt) * 32 + lane) * 4] = *(const float4*)acc[mt][gt];
        __syncthreads();       // all warps passed all waits + finished GEMM

        float fin[4][2];
        #pragma unroll
        for (int gt = 0; gt < 4; gt++) {
            float2 s = make_float2(0.f, 0.f);
            #pragma unroll
            for (int j = 0; j < 4; j++) {
                float2 v = *(const float2*)&((float*)(Aswbase + (rhh_r + 2 * j) * P2_RING))[
                            ((mt_r * 4 + gt) * 32 + lane) * 4 + hb_r * 2];
                s.x += v.x; s.y += v.y;
            }
            fin[gt][0] = s.x; fin[gt][1] = s.y;
        }

        // --- Fused peephole cell update (h ring store first)
        float hv[2];
        #pragma unroll
        for (int q = 0; q < 2; q++) {
            float xf = ((const float*)&xv[0])[q];
            float xi = ((const float*)&xv[1])[q];
            float xo = ((const float*)&xv[2])[q];
            float xc = ((const float*)&xv[3])[q];
            float cp = creg[q];
            float fg = sigf(xf + fin[0][q] + pfv[q] * cp);
            float ig = sigf(xi + fin[1][q] + piv[q] * cp);
            float ct = tanh_fast(xc + fin[3][q]);
            float cn = fg * cp + ig * ct;
            float og = sigf(xo + fin[2][q] + pov[q] * cn);
            float hn = og * tanh_fast(cn);
            creg[q] = cn;
            hv[q] = hn;
        }
        *(__half2*)&hdst[bown * NN + nA] = __floats2half2_rn(hv[0], hv[1]);

        // Order all h stores before the flag release, then release ASAP.
        __syncthreads();
        if (tid == 0) st_rel(&g_flags[cta * 8], (unsigned)(t + 1));

        // out[] store off the critical path
        *(float2*)&out[((size_t)bown * TT + t) * NN + nA] = make_float2(hv[0], hv[1]);
    }
}

// ---------------------------------------------------------------------------
// Launch. Input order detected from in_sizes (dict vs signature order).
// ---------------------------------------------------------------------------
extern "C" void kernel_launch(void* const* d_in, const int* in_sizes, int n_in,
                              void* d_out, int out_size) {
    const float* x   = (const float*)d_in[0];
    const float* c0  = (const float*)d_in[1];
    const float* h0  = (const float*)d_in[2];

    const float *Wfx, *bf, *Wix, *bi, *Wox, *bo, *Wcx, *bc;
    const float *Wfh, *Wih, *Woh, *Wch, *wcf, *wci, *wco;

    if (in_sizes[5] == NN * NN) {
        Wfx = (const float*)d_in[3];  bf  = (const float*)d_in[4];  Wfh = (const float*)d_in[5];
        Wix = (const float*)d_in[6];  bi  = (const float*)d_in[7];  Wih = (const float*)d_in[8];
        Wox = (const float*)d_in[9];  bo  = (const float*)d_in[10]; Woh = (const float*)d_in[11];
        Wcx = (const float*)d_in[12]; bc  = (const float*)d_in[13]; Wch = (const float*)d_in[14];
        wcf = (const float*)d_in[15]; wci = (const float*)d_in[16]; wco = (const float*)d_in[17];
    } else {
        Wfx = (const float*)d_in[3];  bf  = (const float*)d_in[4];
        Wix = (const float*)d_in[5];  bi  = (const float*)d_in[6];
        Wox = (const float*)d_in[7];  bo  = (const float*)d_in[8];
        Wcx = (const float*)d_in[9];  bc  = (const float*)d_in[10];
        Wfh = (const float*)d_in[11]; Wih = (const float*)d_in[12];
        Woh = (const float*)d_in[13]; Wch = (const float*)d_in[14];
        wcf = (const float*)d_in[15]; wci = (const float*)d_in[16]; wco = (const float*)d_in[17];
    }
    float* out = (float*)d_out;

    cudaFuncSetAttribute(xproj_kernel, cudaFuncAttributeMaxDynamicSharedMemorySize, P1_SMEMB);
    cudaFuncSetAttribute(lstm_kernel,  cudaFuncAttributeMaxDynamicSharedMemorySize, P2_SMEMB);

    init_kernel<<<256, 256>>>(h0);
    conv_x_kernel<<<(BB * TT * DD) / 256, 256>>>(x);
    conv_w_kernel<<<(4 * NN * DD) / 256, 256>>>(Wfx, Wix, Wox, Wcx);

    dim3 g1(256, 32);
    xproj_kernel<<<g1, 256, P1_SMEMB>>>(bf, bi, bo, bc);

    lstm_kernel<<<128, 256, P2_SMEMB>>>(c0, Wfh, Wih, Woh, Wch, wcf, wci, wco, out);
}

// round 12
// speedup vs baseline: 1.0591x; 1.0591x over previous
#include <cuda_runtime.h>
#include <cuda_fp16.h>
#include <cstdint>
#include <cstddef>

// Problem shapes (fixed): B=64, T=512, D=512, N=1024, 4N=4096
#define BB 64
#define TT 512
#define DD 512
#define NN 1024
#define GG 4096

// ---------------------------------------------------------------------------
// Device-global scratch
// ---------------------------------------------------------------------------
__device__ float    g_xp[(size_t)TT * BB * GG];   // [T][B][4N] input projections (fp32)
__device__ __half   g_xh[(size_t)BB * TT * DD];   // x converted to fp16
__device__ __half   g_wxt[(size_t)4 * NN * DD];   // Wx gates transposed [gate][n][k] fp16
__device__ __half   g_hbuf[2][BB * NN];           // parity double-buffered h (fp16)
__device__ unsigned g_flags[128 * 8];             // per-CTA step flags, padded to 32B

// ---------------------------------------------------------------------------
// Helpers
// ---------------------------------------------------------------------------
static __device__ __forceinline__ unsigned h2u(__half2 h) { return *(unsigned*)&h; }

static __device__ __forceinline__ float sigf(float x) { return 1.0f / (1.0f + __expf(-x)); }
static __device__ __forceinline__ float tanh_fast(float x) { return 2.0f * sigf(2.0f * x) - 1.0f; }

static __device__ __forceinline__ unsigned smaddr(const void* p) {
    return (unsigned)__cvta_generic_to_shared(p);
}
#define CP16(d, s)  asm volatile("cp.async.cg.shared.global [%0], [%1], 16;" :: "r"(d), "l"(s))
#define CPCOMMIT()  asm volatile("cp.async.commit_group;")

template <int NPend>
static __device__ __forceinline__ void cpwait() {
    asm volatile("cp.async.wait_group %0;" :: "n"(NPend));
}

// ldmatrix x4: 4 8x8 b16 tiles -> 4 regs (lane l of each tile: row l>>2, pair l&3)
static __device__ __forceinline__ void ldsm4(unsigned* r, unsigned addr) {
    asm volatile("ldmatrix.sync.aligned.m8n8.x4.shared.b16 {%0,%1,%2,%3}, [%4];"
        : "=r"(r[0]), "=r"(r[1]), "=r"(r[2]), "=r"(r[3]) : "r"(addr));
}

// fp16 mma m16n8k16, fp32 accumulate (in place)
static __device__ __forceinline__ void mma16(float* d, const unsigned* a, unsigned b0, unsigned b1) {
    asm volatile(
        "mma.sync.aligned.m16n8k16.row.col.f32.f16.f16.f32 "
        "{%0,%1,%2,%3},{%4,%5,%6,%7},{%8,%9},{%0,%1,%2,%3};"
        : "+f"(d[0]), "+f"(d[1]), "+f"(d[2]), "+f"(d[3])
        : "r"(a[0]), "r"(a[1]), "r"(a[2]), "r"(a[3]), "r"(b0), "r"(b1));
}

static __device__ __forceinline__ unsigned ld_acq(const unsigned* p) {
    unsigned v;
    asm volatile("ld.global.acquire.gpu.u32 %0, [%1];" : "=r"(v) : "l"(p));
    return v;
}
static __device__ __forceinline__ void st_rel(unsigned* p, unsigned v) {
    asm volatile("st.global.release.gpu.u32 [%0], %1;" :: "l"(p), "r"(v));
}

// ---------------------------------------------------------------------------
// Init + input conversion kernels (run every replay; cheap)
// ---------------------------------------------------------------------------
__global__ void init_kernel(const float* __restrict__ h0) {
    int i = blockIdx.x * 256 + threadIdx.x;       // 65536 threads == BB*NN
    g_hbuf[0][i] = __float2half_rn(h0[i]);
    if (i < 128 * 8) g_flags[i] = 0u;
}

__global__ void conv_x_kernel(const float* __restrict__ x) {
    size_t i = (size_t)blockIdx.x * 256 + threadIdx.x;   // BB*TT*DD threads
    g_xh[i] = __float2half_rn(x[i]);
}

// g_wxt[gate][n][k] = fp16(Wgate[k][n])
__global__ void conv_w_kernel(
    const float* __restrict__ Wfx, const float* __restrict__ Wix,
    const float* __restrict__ Wox, const float* __restrict__ Wcx)
{
    size_t e = (size_t)blockIdx.x * 256 + threadIdx.x;   // 4*NN*DD threads
    int k    = (int)(e & (DD - 1));
    int n    = (int)((e >> 9) & (NN - 1));
    int gate = (int)(e >> 19);
    const float* W = (gate == 0) ? Wfx : (gate == 1) ? Wix : (gate == 2) ? Wox : Wcx;
    g_wxt[e] = __float2half_rn(W[(size_t)k * NN + n]);
}

// ---------------------------------------------------------------------------
// Phase 1: xp = x @ [Wfx|Wix|Wox|Wcx] + bias  (fp16 m16n8k16, fp32 acc)
// grid (256 m-blocks, 32 n-blocks), 256 threads, BM=BN=128, BK=32 halfs.
// Ring-4 single-sync pipeline, stride-20 rows (conflict-free ldsm).
// ---------------------------------------------------------------------------
#define P1_TSTR  20                       // words per row
#define P1_TILE  (128 * P1_TSTR)          // 2560 words per tile
#define P1_SMEMB (4 * 2 * P1_TILE * 4)    // 81920 bytes (4 slots x (A+B))

__global__ void __launch_bounds__(256, 2) xproj_kernel(
    const float* __restrict__ bf, const float* __restrict__ bi,
    const float* __restrict__ bo, const float* __restrict__ bc)
{
    extern __shared__ unsigned smu[];
    unsigned* AsP = smu;                      // [4][128][20]
    unsigned* BsP = smu + 4 * P1_TILE;        // [4][128][20]

    const int tid  = threadIdx.x;
    const int warp = tid >> 5, lane = tid & 31;
    const int g    = lane >> 2, tig = lane & 3;
    const int wm   = warp >> 1, wn = warp & 1;
    const int M0   = blockIdx.x * 128;
    const int gate = blockIdx.y >> 3;
    const int nc0  = (blockIdx.y & 7) * 128;
    const __half* Wt  = g_wxt + (size_t)gate * NN * DD;
    const float* bias = (gate == 0) ? bf : (gate == 1) ? bi : (gate == 2) ? bo : bc;

    const unsigned sb = smaddr(smu);
    const unsigned aoff = sb + (((wm * 32 + (lane & 15)) * P1_TSTR + (lane >> 4) * 4) << 2);
    const unsigned boff0 = sb + ((4 * P1_TILE +
                     ((wn * 64 + (lane & 7) + ((lane >> 4) & 1) * 8) * P1_TSTR +
                      ((lane >> 3) & 1) * 4)) << 2);

    float acc[2][8][4];
    #pragma unroll
    for (int a = 0; a < 2; a++)
        #pragma unroll
        for (int b = 0; b < 8; b++)
            #pragma unroll
            for (int q = 0; q < 4; q++) acc[a][b][q] = 0.0f;

    auto stage = [&](int c) {
        const int k0 = c * 32;                           // halfs
        const int slot = c & 3;
        unsigned* Ad = AsP + slot * P1_TILE;
        unsigned* Bd = BsP + slot * P1_TILE;
        #pragma unroll
        for (int i = 0; i < 2; i++) {
            int s = tid + 256 * i;                       // 0..511: 128 rows x 4 segs
            int row = s >> 2, seg = s & 3;
            CP16(smaddr(Ad + row * P1_TSTR + seg * 4),
                 g_xh + (size_t)(M0 + row) * DD + k0 + seg * 8);
            CP16(smaddr(Bd + row * P1_TSTR + seg * 4),
                 Wt + (size_t)(nc0 + row) * DD + k0 + seg * 8);
        }
        CPCOMMIT();
    };

    stage(0); stage(1);
    for (int c = 0; c < 16; c++) {
        if (c + 2 < 16) stage(c + 2);
        if (c <= 13)      cpwait<2>();
        else if (c == 14) cpwait<1>();
        else              cpwait<0>();
        __syncthreads();
        const unsigned bufB = (unsigned)((c & 3) * P1_TILE * 4);
        #pragma unroll
        for (int ks2 = 0; ks2 < 2; ks2++) {
            const unsigned kB = bufB + ks2 * 32;         // 8 words = 32 bytes
            unsigned a[2][4];
            ldsm4(a[0], aoff + kB);
            ldsm4(a[1], aoff + kB + 16 * P1_TSTR * 4);
            #pragma unroll
            for (int nfp = 0; nfp < 4; nfp++) {
                unsigned b4[4];
                ldsm4(b4, boff0 + kB + nfp * 16 * P1_TSTR * 4);
                mma16(acc[0][2 * nfp],     a[0], b4[0], b4[1]);
                mma16(acc[1][2 * nfp],     a[1], b4[0], b4[1]);
                mma16(acc[0][2 * nfp + 1], a[0], b4[2], b4[3]);
                mma16(acc[1][2 * nfp + 1], a[1], b4[2], b4[3]);
            }
        }
    }

    #pragma unroll
    for (int mf = 0; mf < 2; mf++) {
        #pragma unroll
        for (int rr = 0; rr < 2; rr++) {
            int m = M0 + wm * 32 + mf * 16 + g + rr * 8;
            int b = m >> 9, t = m & 511;
            size_t base = ((size_t)t * BB + b) * GG + (size_t)blockIdx.y * 128;
            #pragma unroll
            for (int nf = 0; nf < 8; nf++) {
                int col = wn * 64 + nf * 8 + 2 * tig;
                float v0 = acc[mf][nf][rr * 2 + 0] + bias[nc0 + col];
                float v1 = acc[mf][nf][rr * 2 + 1] + bias[nc0 + col + 1];
                *(float2*)&g_xp[base + col] = make_float2(v0, v1);
            }
        }
    }
}

// ---------------------------------------------------------------------------
// Phase 2: persistent LSTM recurrence. 128 CTAs x 256 threads (8 warps).
// fp16 h + fp16 Wh fragments, m16n8k16.
//
// 2-ROW x 4-K WARP SPLIT: warp w = (rhh = w&1, kq = w>>1) owns rows
// [32*rhh, +32) x k [256*kq, +256). 8 chunks of 32 rows x 32 k, 4-deep ring.
// TWO 16-LANE PARALLEL PRODUCER WAITS per step (fix of R11's serialized
// per-chunk waits): lanes 0-15 each poll one CTA of the half's 16 producers.
// Half 0 (CTAs [32kq, +16), covers chunks 0-3) waited before initial
// staging; half 1 (CTAs [32kq+16, +16), covers chunks 4-7) waited at the
// end of chunk 0's compute (~4 chunk-times of slack for stragglers).
// Ring-parity safety: h stored into buf[(t+1)&1] only after the reduction
// __syncthreads (all warps passed both waits; union = all 128 CTAs at
// step >= t), so buf[(t-1)&1] is fully consumed before overwrite.
// ---------------------------------------------------------------------------
#define P2_WHU    16384                   // Wh fragment uints: 64 ks x 2 parts x 32 x 4
#define P2_CHW    (32 * 20)               // chunk: 32 rows x 20 words = 640 words
#define P2_RING   (4 * P2_CHW)            // 4-slot ring per warp = 2560 words
#define P2_SMEMW  (P2_WHU + 8 * P2_RING)  // 36864 words
#define P2_SMEMB  (P2_SMEMW * 4)          // 147456 bytes

__global__ void __launch_bounds__(256, 1) lstm_kernel(
    const float* __restrict__ c0,
    const float* __restrict__ Wfh, const float* __restrict__ Wih,
    const float* __restrict__ Woh, const float* __restrict__ Wch,
    const float* __restrict__ wcf, const float* __restrict__ wci,
    const float* __restrict__ wco,
    float* __restrict__ out)
{
    extern __shared__ unsigned smu[];
    unsigned* whfu = smu;                         // fill view
    const uint4* whf4 = (const uint4*)smu;        // [(ks*2+part)*32 + lane]
    unsigned* Aswbase = smu + P2_WHU;             // 8 warp rings

    const int tid  = threadIdx.x;
    const int warp = tid >> 5, lane = tid & 31;
    const int g    = lane >> 2, tig = lane & 3;
    const int cta  = blockIdx.x;
    const int n0   = cta * 8;

    const int rhh = warp & 1;                 // row half (32 rows)
    const int kq  = warp >> 1;                // k quarter (256 halfs)
    const int rowbase = rhh * 32;
    const int kbase   = kq * 256;

    unsigned* Asw = Aswbase + warp * P2_RING;

    // LDSM A-frag base (bytes) for m-tile mt: rows mt*16 + (lane&15), seg (lane>>4)*4
    const unsigned aaddr0 = smaddr(Asw) + (((lane & 15) * 20 + (lane >> 4) * 4) << 2);

    // --- Prologue: build fp16 Wh fragments in SMEM (resident for all steps)
    for (int e = tid; e < P2_WHU; e += 256) {
        int j     = e & 3;
        int lane_ = (e >> 2) & 31;
        int part  = (e >> 7) & 1;
        int ks    = e >> 8;                    // 0..63
        int gate  = part * 2 + (j >> 1);       // 0=f 1=i 2=o 3=c
        int which = j & 1;                     // b0 / b1
        int tg    = lane_ & 3;
        int col   = n0 + (lane_ >> 2);
        int kb    = ks * 16 + 2 * tg + which * 8;
        const float* Wsel = (gate == 0) ? Wfh : (gate == 1) ? Wih : (gate == 2) ? Woh : Wch;
        __half2 v = __floats2half2_rn(Wsel[(size_t)kb * NN + col],
                                      Wsel[(size_t)(kb + 1) * NN + col]);
        whfu[e] = h2u(v);
    }

    // --- Per-thread update-cell ownership: 1 row x 2 cols
    const int bown = (warp >> 1) * 16 + (warp & 1) * 8 + g;
    const int nA   = n0 + 2 * tig;
    // Reduction source selectors (bits of bown)
    const int rhh_r = (warp >> 2) & 1;
    const int mt_r  = (warp >> 1) & 1;
    const int hb_r  = warp & 1;

    float2 cv2 = *(const float2*)&c0[bown * NN + nA];
    float creg[2] = {cv2.x, cv2.y};
    float2 pf2 = *(const float2*)&wcf[nA];
    float2 pi2 = *(const float2*)&wci[nA];
    float2 po2 = *(const float2*)&wco[nA];
    const float pfv[2] = {pf2.x, pf2.y};
    const float piv[2] = {pi2.x, pi2.y};
    const float pov[2] = {po2.x, po2.y};

    __syncthreads();   // whf ready

    // Per-warp producer flag pointer for each half (16 producers per half)
    const unsigned* flag_h0 = &g_flags[(32 * kq + (lane & 15)) * 8];
    const unsigned* flag_h1 = &g_flags[(32 * kq + 16 + (lane & 15)) * 8];

    for (int t = 0; t < TT; t++) {
        const __half* hsrc = g_hbuf[t & 1];
        __half* hdst = g_hbuf[(t + 1) & 1];

        // Prefetch xp BEFORE any wait (no h dependency)
        const float* xpt = g_xp + (size_t)t * BB * GG;
        float2 xv[4];
        #pragma unroll
        for (int nt = 0; nt < 4; nt++)
            xv[nt] = *(const float2*)&xpt[(size_t)bown * GG + nt * NN + nA];

        float acc[2][4][4] __attribute__((aligned(16)));
        #pragma unroll
        for (int a = 0; a < 2; a++)
            #pragma unroll
            for (int b = 0; b < 4; b++)
                #pragma unroll
                for (int q = 0; q < 4; q++) acc[a][b][q] = 0.0f;

        // Stage chunk c: rows rowbase..+32, k halfs kbase + c*32..+32
        auto stageh = [&](int c) {
            const __half* src = hsrc + (size_t)rowbase * NN + kbase + c * 32;
            unsigned* dst = Asw + (c & 3) * P2_CHW;
            #pragma unroll
            for (int i = 0; i < 4; i++) {
                int s = lane + 32 * i;                // 32 rows x 4 16B-segs
                int row = s >> 2, seg = s & 3;
                CP16(smaddr(dst + row * 20 + seg * 4), src + (size_t)row * NN + seg * 8);
            }
            CPCOMMIT();
        };

        // Half-0 producers (chunks 0-3): one parallel 16-lane poll
        if (t > 0) {
            const unsigned tgt = (unsigned)t;
            if (lane < 16) { while (ld_acq(flag_h0) < tgt) { } }
            __syncwarp();
        }
        stageh(0); stageh(1); stageh(2); stageh(3);

        #pragma unroll
        for (int c = 0; c < 8; c++) {
            if (c <= 4)      cpwait<3>();
            else if (c == 5) cpwait<2>();
            else if (c == 6) cpwait<1>();
            else             cpwait<0>();
            __syncwarp();     // cp.async visibility across lanes before collective ldsm
            const unsigned abase = aaddr0 + (unsigned)((c & 3) * P2_CHW * 4);
            #pragma unroll
            for (int ks2 = 0; ks2 < 2; ks2++) {
                const int ks = kq * 16 + c * 2 + ks2;
                const uint4 uA = whf4[(ks * 2 + 0) * 32 + lane];
                const uint4 uB = whf4[(ks * 2 + 1) * 32 + lane];
                #pragma unroll
                for (int mt = 0; mt < 2; mt++) {
                    unsigned a[4];
                    ldsm4(a, abase + (unsigned)(mt * 16 * 20 * 4) + ks2 * 32);
                    mma16(acc[mt][0], a, uA.x, uA.y);   // forget
                    mma16(acc[mt][1], a, uA.z, uA.w);   // input
                    mma16(acc[mt][2], a, uB.x, uB.y);   // output
                    mma16(acc[mt][3], a, uB.z, uB.w);   // cell
                }
            }
            // Half-1 producers (chunks 4-7): waited once, after chunk 0's compute
            if (c == 0 && t > 0) {
                const unsigned tgt = (unsigned)t;
                if (lane < 16) { while (ld_acq(flag_h1) < tgt) { } }
                __syncwarp();
            }
            if (c + 4 < 8) stageh(c + 4);
        }

        // --- Cross-warp (4-way) reduction via smem (reuse own ring region)
        float* Aswf = (float*)Asw;
        #pragma unroll
        for (int mt = 0; mt < 2; mt++)
            #pragma unroll
            for (int gt = 0; gt < 4; gt++)
                *(float4*)&Aswf[((mt * 4 + gt) * 32 + lane) * 4] = *(const float4*)acc[mt][gt];
        __syncthreads();       // all warps passed both waits + finished GEMM

        float fin[4][2];
        #pragma unroll
        for (int gt = 0; gt < 4; gt++) {
            float2 s = make_float2(0.f, 0.f);
            #pragma unroll
            for (int j = 0; j < 4; j++) {
                float2 v = *(const float2*)&((float*)(Aswbase + (rhh_r + 2 * j) * P2_RING))[
                            ((mt_r * 4 + gt) * 32 + lane) * 4 + hb_r * 2];
                s.x += v.x; s.y += v.y;
            }
            fin[gt][0] = s.x; fin[gt][1] = s.y;
        }

        // --- Fused peephole cell update (h ring store first)
        float hv[2];
        #pragma unroll
        for (int q = 0; q < 2; q++) {
            float xf = ((const float*)&xv[0])[q];
            float xi = ((const float*)&xv[1])[q];
            float xo = ((const float*)&xv[2])[q];
            float xc = ((const float*)&xv[3])[q];
            float cp = creg[q];
            float fg = sigf(xf + fin[0][q] + pfv[q] * cp);
            float ig = sigf(xi + fin[1][q] + piv[q] * cp);
            float ct = tanh_fast(xc + fin[3][q]);
            float cn = fg * cp + ig * ct;
            float og = sigf(xo + fin[2][q] + pov[q] * cn);
            float hn = og * tanh_fast(cn);
            creg[q] = cn;
            hv[q] = hn;
        }
        *(__half2*)&hdst[bown * NN + nA] = __floats2half2_rn(hv[0], hv[1]);

        // Order all h stores before the flag release, then release ASAP.
        __syncthreads();
        if (tid == 0) st_rel(&g_flags[cta * 8], (unsigned)(t + 1));

        // out[] store off the critical path
        *(float2*)&out[((size_t)bown * TT + t) * NN + nA] = make_float2(hv[0], hv[1]);
    }
}

// ---------------------------------------------------------------------------
// Launch. Input order detected from in_sizes (dict vs signature order).
// ---------------------------------------------------------------------------
extern "C" void kernel_launch(void* const* d_in, const int* in_sizes, int n_in,
                              void* d_out, int out_size) {
    const float* x   = (const float*)d_in[0];
    const float* c0  = (const float*)d_in[1];
    const float* h0  = (const float*)d_in[2];

    const float *Wfx, *bf, *Wix, *bi, *Wox, *bo, *Wcx, *bc;
    const float *Wfh, *Wih, *Woh, *Wch, *wcf, *wci, *wco;

    if (in_sizes[5] == NN * NN) {
        Wfx = (const float*)d_in[3];  bf  = (const float*)d_in[4];  Wfh = (const float*)d_in[5];
        Wix = (const float*)d_in[6];  bi  = (const float*)d_in[7];  Wih = (const float*)d_in[8];
        Wox = (const float*)d_in[9];  bo  = (const float*)d_in[10]; Woh = (const float*)d_in[11];
        Wcx = (const float*)d_in[12]; bc  = (const float*)d_in[13]; Wch = (const float*)d_in[14];
        wcf = (const float*)d_in[15]; wci = (const float*)d_in[16]; wco = (const float*)d_in[17];
    } else {
        Wfx = (const float*)d_in[3];  bf  = (const float*)d_in[4];
        Wix = (const float*)d_in[5];  bi  = (const float*)d_in[6];
        Wox = (const float*)d_in[7];  bo  = (const float*)d_in[8];
        Wcx = (const float*)d_in[9];  bc  = (const float*)d_in[10];
        Wfh = (const float*)d_in[11]; Wih = (const float*)d_in[12];
        Woh = (const float*)d_in[13]; Wch = (const float*)d_in[14];
        wcf = (const float*)d_in[15]; wci = (const float*)d_in[16]; wco = (const float*)d_in[17];
    }
    float* out = (float*)d_out;

    cudaFuncSetAttribute(xproj_kernel, cudaFuncAttributeMaxDynamicSharedMemorySize, P1_SMEMB);
    cudaFuncSetAttribute(lstm_kernel,  cudaFuncAttributeMaxDynamicSharedMemorySize, P2_SMEMB);

    init_kernel<<<256, 256>>>(h0);
    conv_x_kernel<<<(BB * TT * DD) / 256, 256>>>(x);
    conv_w_kernel<<<(4 * NN * DD) / 256, 256>>>(Wfx, Wix, Wox, Wcx);

    dim3 g1(256, 32);
    xproj_kernel<<<g1, 256, P1_SMEMB>>>(bf, bi, bo, bc);

    lstm_kernel<<<128, 256, P2_SMEMB>>>(c0, Wfh, Wih, Woh, Wch, wcf, wci, wco, out);
}

// round 13
// speedup vs baseline: 1.1661x; 1.1009x over previous
#include <cuda_runtime.h>
#include <cuda_fp16.h>
#include <cstdint>
#include <cstddef>

// Problem shapes (fixed): B=64, T=512, D=512, N=1024, 4N=4096
#define BB 64
#define TT 512
#define DD 512
#define NN 1024
#define GG 4096

// ---------------------------------------------------------------------------
// Device-global scratch
// ---------------------------------------------------------------------------
__device__ float    g_xp[(size_t)TT * BB * GG];   // [T][B][4N] input projections (fp32)
__device__ __half   g_xh[(size_t)BB * TT * DD];   // x converted to fp16
__device__ __half   g_wxt[(size_t)4 * NN * DD];   // Wx gates transposed [gate][n][k] fp16
__device__ __half   g_hbuf[2][BB * NN];           // parity double-buffered h (fp16)
__device__ unsigned g_flags[128 * 8];             // per-CTA step counters (8 adds/step), 32B padded

// ---------------------------------------------------------------------------
// Helpers
// ---------------------------------------------------------------------------
static __device__ __forceinline__ unsigned h2u(__half2 h) { return *(unsigned*)&h; }

static __device__ __forceinline__ float sigf(float x) { return 1.0f / (1.0f + __expf(-x)); }
static __device__ __forceinline__ float tanh_fast(float x) { return 2.0f * sigf(2.0f * x) - 1.0f; }

static __device__ __forceinline__ unsigned smaddr(const void* p) {
    return (unsigned)__cvta_generic_to_shared(p);
}
#define CP16(d, s)  asm volatile("cp.async.cg.shared.global [%0], [%1], 16;" :: "r"(d), "l"(s))
#define CPCOMMIT()  asm volatile("cp.async.commit_group;")

template <int NPend>
static __device__ __forceinline__ void cpwait() {
    asm volatile("cp.async.wait_group %0;" :: "n"(NPend));
}

// ldmatrix x4: 4 8x8 b16 tiles -> 4 regs (lane l of each tile: row l>>2, pair l&3)
static __device__ __forceinline__ void ldsm4(unsigned* r, unsigned addr) {
    asm volatile("ldmatrix.sync.aligned.m8n8.x4.shared.b16 {%0,%1,%2,%3}, [%4];"
        : "=r"(r[0]), "=r"(r[1]), "=r"(r[2]), "=r"(r[3]) : "r"(addr));
}

// fp16 mma m16n8k16, fp32 accumulate (in place)
static __device__ __forceinline__ void mma16(float* d, const unsigned* a, unsigned b0, unsigned b1) {
    asm volatile(
        "mma.sync.aligned.m16n8k16.row.col.f32.f16.f16.f32 "
        "{%0,%1,%2,%3},{%4,%5,%6,%7},{%8,%9},{%0,%1,%2,%3};"
        : "+f"(d[0]), "+f"(d[1]), "+f"(d[2]), "+f"(d[3])
        : "r"(a[0]), "r"(a[1]), "r"(a[2]), "r"(a[3]), "r"(b0), "r"(b1));
}

static __device__ __forceinline__ unsigned ld_acq(const unsigned* p) {
    unsigned v;
    asm volatile("ld.global.acquire.gpu.u32 %0, [%1];" : "=r"(v) : "l"(p));
    return v;
}
static __device__ __forceinline__ void red_add_rel(unsigned* p, unsigned v) {
    asm volatile("red.release.gpu.global.add.u32 [%0], %1;" :: "l"(p), "r"(v));
}

// ---------------------------------------------------------------------------
// Init + input conversion kernels (run every replay; cheap)
// ---------------------------------------------------------------------------
__global__ void init_kernel(const float* __restrict__ h0) {
    int i = blockIdx.x * 256 + threadIdx.x;       // 65536 threads == BB*NN
    g_hbuf[0][i] = __float2half_rn(h0[i]);
    if (i < 128 * 8) g_flags[i] = 0u;
}

__global__ void conv_x_kernel(const float* __restrict__ x) {
    size_t i = (size_t)blockIdx.x * 256 + threadIdx.x;   // BB*TT*DD threads
    g_xh[i] = __float2half_rn(x[i]);
}

// g_wxt[gate][n][k] = fp16(Wgate[k][n])
__global__ void conv_w_kernel(
    const float* __restrict__ Wfx, const float* __restrict__ Wix,
    const float* __restrict__ Wox, const float* __restrict__ Wcx)
{
    size_t e = (size_t)blockIdx.x * 256 + threadIdx.x;   // 4*NN*DD threads
    int k    = (int)(e & (DD - 1));
    int n    = (int)((e >> 9) & (NN - 1));
    int gate = (int)(e >> 19);
    const float* W = (gate == 0) ? Wfx : (gate == 1) ? Wix : (gate == 2) ? Wox : Wcx;
    g_wxt[e] = __float2half_rn(W[(size_t)k * NN + n]);
}

// ---------------------------------------------------------------------------
// Phase 1: xp = x @ [Wfx|Wix|Wox|Wcx] + bias  (fp16 m16n8k16, fp32 acc)
// grid (256 m-blocks, 32 n-blocks), 256 threads, BM=BN=128, BK=64 halfs.
// Ring-3 single-sync pipeline: stage(c+1) at top of iter c, ONE syncthreads
// per chunk; slot reuse (period 3) separated by the intervening barriers.
// Stride-36 rows (32 data + 4 pad words): ldsm banks (4r + 8ks2 + 4s) mod 32
// distinct within every 8-lane phase -> conflict-free for all 4 k-steps.
// ---------------------------------------------------------------------------
#define P1_TSTR  36                       // words per row
#define P1_TILE  (128 * P1_TSTR)          // 4608 words per tile
#define P1_SMEMB (3 * 2 * P1_TILE * 4)    // 110592 bytes (3 slots x (A+B))

__global__ void __launch_bounds__(256, 2) xproj_kernel(
    const float* __restrict__ bf, const float* __restrict__ bi,
    const float* __restrict__ bo, const float* __restrict__ bc)
{
    extern __shared__ unsigned smu[];
    unsigned* AsP = smu;                      // [3][128][36]
    unsigned* BsP = smu + 3 * P1_TILE;        // [3][128][36]

    const int tid  = threadIdx.x;
    const int warp = tid >> 5, lane = tid & 31;
    const int g    = lane >> 2, tig = lane & 3;
    const int wm   = warp >> 1, wn = warp & 1;
    const int M0   = blockIdx.x * 128;
    const int gate = blockIdx.y >> 3;
    const int nc0  = (blockIdx.y & 7) * 128;
    const __half* Wt  = g_wxt + (size_t)gate * NN * DD;
    const float* bias = (gate == 0) ? bf : (gate == 1) ? bi : (gate == 2) ? bo : bc;

    const unsigned sb = smaddr(smu);
    const unsigned aoff = sb + (((wm * 32 + (lane & 15)) * P1_TSTR + (lane >> 4) * 4) << 2);
    const unsigned boff0 = sb + ((3 * P1_TILE +
                     ((wn * 64 + (lane & 7) + ((lane >> 4) & 1) * 8) * P1_TSTR +
                      ((lane >> 3) & 1) * 4)) << 2);

    float acc[2][8][4];
    #pragma unroll
    for (int a = 0; a < 2; a++)
        #pragma unroll
        for (int b = 0; b < 8; b++)
            #pragma unroll
            for (int q = 0; q < 4; q++) acc[a][b][q] = 0.0f;

    auto stage = [&](int c) {
        const int k0 = c * 64;                           // halfs
        const int slot = c % 3;
        unsigned* Ad = AsP + slot * P1_TILE;
        unsigned* Bd = BsP + slot * P1_TILE;
        #pragma unroll
        for (int i = 0; i < 4; i++) {
            int s = tid + 256 * i;                       // 0..1023: 128 rows x 8 segs
            int row = s >> 3, seg = s & 7;
            CP16(smaddr(Ad + row * P1_TSTR + seg * 4),
                 g_xh + (size_t)(M0 + row) * DD + k0 + seg * 8);
            CP16(smaddr(Bd + row * P1_TSTR + seg * 4),
                 Wt + (size_t)(nc0 + row) * DD + k0 + seg * 8);
        }
        CPCOMMIT();
    };

    stage(0);
    for (int c = 0; c < 8; c++) {
        if (c + 1 < 8) { stage(c + 1); cpwait<1>(); }
        else           { cpwait<0>(); }
        __syncthreads();
        const unsigned bufB = (unsigned)((c % 3) * P1_TILE * 4);
        #pragma unroll
        for (int ks2 = 0; ks2 < 4; ks2++) {
            const unsigned kB = bufB + ks2 * 32;         // 8 words = 32 bytes
            unsigned a[2][4];
            ldsm4(a[0], aoff + kB);
            ldsm4(a[1], aoff + kB + 16 * P1_TSTR * 4);
            #pragma unroll
            for (int nfp = 0; nfp < 4; nfp++) {
                unsigned b4[4];
                ldsm4(b4, boff0 + kB + nfp * 16 * P1_TSTR * 4);
                mma16(acc[0][2 * nfp],     a[0], b4[0], b4[1]);
                mma16(acc[1][2 * nfp],     a[1], b4[0], b4[1]);
                mma16(acc[0][2 * nfp + 1], a[0], b4[2], b4[3]);
                mma16(acc[1][2 * nfp + 1], a[1], b4[2], b4[3]);
            }
        }
    }

    #pragma unroll
    for (int mf = 0; mf < 2; mf++) {
        #pragma unroll
        for (int rr = 0; rr < 2; rr++) {
            int m = M0 + wm * 32 + mf * 16 + g + rr * 8;
            int b = m >> 9, t = m & 511;
            size_t base = ((size_t)t * BB + b) * GG + (size_t)blockIdx.y * 128;
            #pragma unroll
            for (int nf = 0; nf < 8; nf++) {
                int col = wn * 64 + nf * 8 + 2 * tig;
                float v0 = acc[mf][nf][rr * 2 + 0] + bias[nc0 + col];
                float v1 = acc[mf][nf][rr * 2 + 1] + bias[nc0 + col + 1];
                *(float2*)&g_xp[base + col] = make_float2(v0, v1);
            }
        }
    }
}

// ---------------------------------------------------------------------------
// Phase 2: persistent LSTM recurrence. 128 CTAs x 256 threads (8 warps).
// fp16 h + fp16 Wh fragments, m16n8k16. 2-row x 4-k warp split, 8 chunks,
// 4-deep ring, two 16-lane parallel producer waits per step.
//
// ONE barrier per step: reduction partials live in a dedicated
// parity-double-buffered redbuf (step t uses redbuf[t&1]); intra-CTA skew
// is <= 1 phase (no warp passes step t+1's reduction barrier until every
// warp finished step t), so parity-2 suffices and ring restaging never
// collides with straggler reads. Release is per-warp: after own h-store,
// __syncwarp (memory-ordering barrier) then lane0 red.release-adds the CTA
// counter; consumers poll counter >= 8t (8 warps x 1 add per step).
// Ring-parity (global) safety unchanged: h stored into buf[(t+1)&1] only
// after this CTA's reduction barrier, which follows all warps' producer
// waits (union = all 128 CTAs at step >= t).
// ---------------------------------------------------------------------------
#define P2_WHU    16384                   // Wh fragment uints: 64 ks x 2 parts x 32 x 4
#define P2_CHW    (32 * 20)               // chunk: 32 rows x 20 words = 640 words
#define P2_RING   (4 * P2_CHW)            // 4-slot ring per warp = 2560 words
#define P2_REDW   (2 * 8 * 1024)          // redbuf: 2 parity x 8 warps x 1024 floats
#define P2_SMEMW  (P2_WHU + 8 * P2_RING + P2_REDW)  // 53248 words
#define P2_SMEMB  (P2_SMEMW * 4)          // 212992 bytes

__global__ void __launch_bounds__(256, 1) lstm_kernel(
    const float* __restrict__ c0,
    const float* __restrict__ Wfh, const float* __restrict__ Wih,
    const float* __restrict__ Woh, const float* __restrict__ Wch,
    const float* __restrict__ wcf, const float* __restrict__ wci,
    const float* __restrict__ wco,
    float* __restrict__ out)
{
    extern __shared__ unsigned smu[];
    unsigned* whfu = smu;                         // fill view
    const uint4* whf4 = (const uint4*)smu;        // [(ks*2+part)*32 + lane]
    unsigned* Aswbase = smu + P2_WHU;             // 8 warp rings
    float* redf = (float*)(smu + P2_WHU + 8 * P2_RING);  // [2][8][1024]

    const int tid  = threadIdx.x;
    const int warp = tid >> 5, lane = tid & 31;
    const int g    = lane >> 2, tig = lane & 3;
    const int cta  = blockIdx.x;
    const int n0   = cta * 8;

    const int rhh = warp & 1;                 // row half (32 rows)
    const int kq  = warp >> 1;                // k quarter (256 halfs)
    const int rowbase = rhh * 32;
    const int kbase   = kq * 256;

    unsigned* Asw = Aswbase + warp * P2_RING;

    // LDSM A-frag base (bytes) for m-tile mt: rows mt*16 + (lane&15), seg (lane>>4)*4
    const unsigned aaddr0 = smaddr(Asw) + (((lane & 15) * 20 + (lane >> 4) * 4) << 2);

    // --- Prologue: build fp16 Wh fragments in SMEM (resident for all steps)
    for (int e = tid; e < P2_WHU; e += 256) {
        int j     = e & 3;
        int lane_ = (e >> 2) & 31;
        int part  = (e >> 7) & 1;
        int ks    = e >> 8;                    // 0..63
        int gate  = part * 2 + (j >> 1);       // 0=f 1=i 2=o 3=c
        int which = j & 1;                     // b0 / b1
        int tg    = lane_ & 3;
        int col   = n0 + (lane_ >> 2);
        int kb    = ks * 16 + 2 * tg + which * 8;
        const float* Wsel = (gate == 0) ? Wfh : (gate == 1) ? Wih : (gate == 2) ? Woh : Wch;
        __half2 v = __floats2half2_rn(Wsel[(size_t)kb * NN + col],
                                      Wsel[(size_t)(kb + 1) * NN + col]);
        whfu[e] = h2u(v);
    }

    // --- Per-thread update-cell ownership: 1 row x 2 cols
    const int bown = (warp >> 1) * 16 + (warp & 1) * 8 + g;
    const int nA   = n0 + 2 * tig;
    // Reduction source selectors (bits of bown)
    const int rhh_r = (warp >> 2) & 1;
    const int mt_r  = (warp >> 1) & 1;
    const int hb_r  = warp & 1;

    float2 cv2 = *(const float2*)&c0[bown * NN + nA];
    float creg[2] = {cv2.x, cv2.y};
    float2 pf2 = *(const float2*)&wcf[nA];
    float2 pi2 = *(const float2*)&wci[nA];
    float2 po2 = *(const float2*)&wco[nA];
    const float pfv[2] = {pf2.x, pf2.y};
    const float piv[2] = {pi2.x, pi2.y};
    const float pov[2] = {po2.x, po2.y};

    __syncthreads();   // whf ready

    // Per-warp producer flag pointers (16 producers per half)
    const unsigned* flag_h0 = &g_flags[(32 * kq + (lane & 15)) * 8];
    const unsigned* flag_h1 = &g_flags[(32 * kq + 16 + (lane & 15)) * 8];

    for (int t = 0; t < TT; t++) {
        const __half* hsrc = g_hbuf[t & 1];
        __half* hdst = g_hbuf[(t + 1) & 1];
        float* redp = redf + (t & 1) * (8 * 1024);

        // Prefetch xp BEFORE any wait (no h dependency)
        const float* xpt = g_xp + (size_t)t * BB * GG;
        float2 xv[4];
        #pragma unroll
        for (int nt = 0; nt < 4; nt++)
            xv[nt] = *(const float2*)&xpt[(size_t)bown * GG + nt * NN + nA];

        float acc[2][4][4] __attribute__((aligned(16)));
        #pragma unroll
        for (int a = 0; a < 2; a++)
            #pragma unroll
            for (int b = 0; b < 4; b++)
                #pragma unroll
                for (int q = 0; q < 4; q++) acc[a][b][q] = 0.0f;

        // Stage chunk c: rows rowbase..+32, k halfs kbase + c*32..+32
        auto stageh = [&](int c) {
            const __half* src = hsrc + (size_t)rowbase * NN + kbase + c * 32;
            unsigned* dst = Asw + (c & 3) * P2_CHW;
            #pragma unroll
            for (int i = 0; i < 4; i++) {
                int s = lane + 32 * i;                // 32 rows x 4 16B-segs
                int row = s >> 2, seg = s & 3;
                CP16(smaddr(dst + row * 20 + seg * 4), src + (size_t)row * NN + seg * 8);
            }
            CPCOMMIT();
        };

        // Half-0 producers (chunks 0-3): one parallel 16-lane poll
        if (t > 0) {
            const unsigned tgt = (unsigned)(8 * t);
            if (lane < 16) { while (ld_acq(flag_h0) < tgt) { } }
            __syncwarp();
        }
        stageh(0); stageh(1); stageh(2); stageh(3);

        #pragma unroll
        for (int c = 0; c < 8; c++) {
            if (c <= 4)      cpwait<3>();
            else if (c == 5) cpwait<2>();
            else if (c == 6) cpwait<1>();
            else             cpwait<0>();
            __syncwarp();     // cp.async visibility across lanes before collective ldsm
            const unsigned abase = aaddr0 + (unsigned)((c & 3) * P2_CHW * 4);
            #pragma unroll
            for (int ks2 = 0; ks2 < 2; ks2++) {
                const int ks = kq * 16 + c * 2 + ks2;
                const uint4 uA = whf4[(ks * 2 + 0) * 32 + lane];
                const uint4 uB = whf4[(ks * 2 + 1) * 32 + lane];
                #pragma unroll
                for (int mt = 0; mt < 2; mt++) {
                    unsigned a[4];
                    ldsm4(a, abase + (unsigned)(mt * 16 * 20 * 4) + ks2 * 32);
                    mma16(acc[mt][0], a, uA.x, uA.y);   // forget
                    mma16(acc[mt][1], a, uA.z, uA.w);   // input
                    mma16(acc[mt][2], a, uB.x, uB.y);   // output
                    mma16(acc[mt][3], a, uB.z, uB.w);   // cell
                }
            }
            // Half-1 producers (chunks 4-7): waited once, after chunk 0's compute
            if (c == 0 && t > 0) {
                const unsigned tgt = (unsigned)(8 * t);
                if (lane < 16) { while (ld_acq(flag_h1) < tgt) { } }
                __syncwarp();
            }
            if (c + 4 < 8) stageh(c + 4);
        }

        // --- Cross-warp (4-way) reduction via parity redbuf
        #pragma unroll
        for (int mt = 0; mt < 2; mt++)
            #pragma unroll
            for (int gt = 0; gt < 4; gt++)
                *(float4*)&redp[warp * 1024 + ((mt * 4 + gt) * 32 + lane) * 4] =
                    *(const float4*)acc[mt][gt];
        __syncthreads();       // all warps passed both waits + finished GEMM

        float fin[4][2];
        #pragma unroll
        for (int gt = 0; gt < 4; gt++) {
            float2 s = make_float2(0.f, 0.f);
            #pragma unroll
            for (int j = 0; j < 4; j++) {
                float2 v = *(const float2*)&redp[(rhh_r + 2 * j) * 1024 +
                            ((mt_r * 4 + gt) * 32 + lane) * 4 + hb_r * 2];
                s.x += v.x; s.y += v.y;
            }
            fin[gt][0] = s.x; fin[gt][1] = s.y;
        }

        // --- Fused peephole cell update (h ring store first)
        float hv[2];
        #pragma unroll
        for (int q = 0; q < 2; q++) {
            float xf = ((const float*)&xv[0])[q];
            float xi = ((const float*)&xv[1])[q];
            float xo = ((const float*)&xv[2])[q];
            float xc = ((const float*)&xv[3])[q];
            float cp = creg[q];
            float fg = sigf(xf + fin[0][q] + pfv[q] * cp);
            float ig = sigf(xi + fin[1][q] + piv[q] * cp);
            float ct = tanh_fast(xc + fin[3][q]);
            float cn = fg * cp + ig * ct;
            float og = sigf(xo + fin[2][q] + pov[q] * cn);
            float hn = og * tanh_fast(cn);
            creg[q] = cn;
            hv[q] = hn;
        }
        *(__half2*)&hdst[bown * NN + nA] = __floats2half2_rn(hv[0], hv[1]);

        // Per-warp release: syncwarp orders all lanes' h stores, then lane0 adds.
        __syncwarp();
        if (lane == 0) red_add_rel(&g_flags[cta * 8], 1u);

        // out[] store off the critical path
        *(float2*)&out[((size_t)bown * TT + t) * NN + nA] = make_float2(hv[0], hv[1]);
    }
}

// ---------------------------------------------------------------------------
// Launch. Input order detected from in_sizes (dict vs signature order).
// ---------------------------------------------------------------------------
extern "C" void kernel_launch(void* const* d_in, const int* in_sizes, int n_in,
                              void* d_out, int out_size) {
    const float* x   = (const float*)d_in[0];
    const float* c0  = (const float*)d_in[1];
    const float* h0  = (const float*)d_in[2];

    const float *Wfx, *bf, *Wix, *bi, *Wox, *bo, *Wcx, *bc;
    const float *Wfh, *Wih, *Woh, *Wch, *wcf, *wci, *wco;

    if (in_sizes[5] == NN * NN) {
        Wfx = (const float*)d_in[3];  bf  = (const float*)d_in[4];  Wfh = (const float*)d_in[5];
        Wix = (const float*)d_in[6];  bi  = (const float*)d_in[7];  Wih = (const float*)d_in[8];
        Wox = (const float*)d_in[9];  bo  = (const float*)d_in[10]; Woh = (const float*)d_in[11];
        Wcx = (const float*)d_in[12]; bc  = (const float*)d_in[13]; Wch = (const float*)d_in[14];
        wcf = (const float*)d_in[15]; wci = (const float*)d_in[16]; wco = (const float*)d_in[17];
    } else {
        Wfx = (const float*)d_in[3];  bf  = (const float*)d_in[4];
        Wix = (const float*)d_in[5];  bi  = (const float*)d_in[6];
        Wox = (const float*)d_in[7];  bo  = (const float*)d_in[8];
        Wcx = (const float*)d_in[9];  bc  = (const float*)d_in[10];
        Wfh = (const float*)d_in[11]; Wih = (const float*)d_in[12];
        Woh = (const float*)d_in[13]; Wch = (const float*)d_in[14];
        wcf = (const float*)d_in[15]; wci = (const float*)d_in[16]; wco = (const float*)d_in[17];
    }
    float* out = (float*)d_out;

    cudaFuncSetAttribute(xproj_kernel, cudaFuncAttributeMaxDynamicSharedMemorySize, P1_SMEMB);
    cudaFuncSetAttribute(lstm_kernel,  cudaFuncAttributeMaxDynamicSharedMemorySize, P2_SMEMB);

    init_kernel<<<256, 256>>>(h0);
    conv_x_kernel<<<(BB * TT * DD) / 256, 256>>>(x);
    conv_w_kernel<<<(4 * NN * DD) / 256, 256>>>(Wfx, Wix, Wox, Wcx);

    dim3 g1(256, 32);
    xproj_kernel<<<g1, 256, P1_SMEMB>>>(bf, bi, bo, bc);

    lstm_kernel<<<128, 256, P2_SMEMB>>>(c0, Wfh, Wih, Woh, Wch, wcf, wci, wco, out);
}

// round 14
// speedup vs baseline: 1.1667x; 1.0006x over previous
#include <cuda_runtime.h>
#include <cuda_fp16.h>
#include <cstdint>
#include <cstddef>

// Problem shapes (fixed): B=64, T=512, D=512, N=1024, 4N=4096
#define BB 64
#define TT 512
#define DD 512
#define NN 1024
#define GG 4096

// ---------------------------------------------------------------------------
// Device-global scratch
// ---------------------------------------------------------------------------
__device__ float    g_xp[(size_t)TT * BB * GG];   // [T][B][4N] input projections (fp32)
__device__ __half   g_xh[(size_t)BB * TT * DD];   // x converted to fp16
__device__ __half   g_wxt[(size_t)4 * NN * DD];   // Wx gates transposed [gate][n][k] fp16
__device__ __half   g_hbuf[2][BB * NN];           // parity double-buffered h (fp16)
__device__ unsigned g_flags[128 * 8];             // per-CTA per-half step counters, 32B padded

// ---------------------------------------------------------------------------
// Helpers
// ---------------------------------------------------------------------------
static __device__ __forceinline__ unsigned h2u(__half2 h) { return *(unsigned*)&h; }

static __device__ __forceinline__ float sigf(float x) { return 1.0f / (1.0f + __expf(-x)); }
static __device__ __forceinline__ float tanh_fast(float x) { return 2.0f * sigf(2.0f * x) - 1.0f; }

static __device__ __forceinline__ unsigned smaddr(const void* p) {
    return (unsigned)__cvta_generic_to_shared(p);
}
#define CP16(d, s)  asm volatile("cp.async.cg.shared.global [%0], [%1], 16;" :: "r"(d), "l"(s))
#define CPCOMMIT()  asm volatile("cp.async.commit_group;")

template <int NPend>
static __device__ __forceinline__ void cpwait() {
    asm volatile("cp.async.wait_group %0;" :: "n"(NPend));
}

// ldmatrix x4: 4 8x8 b16 tiles -> 4 regs (lane l of each tile: row l>>2, pair l&3)
static __device__ __forceinline__ void ldsm4(unsigned* r, unsigned addr) {
    asm volatile("ldmatrix.sync.aligned.m8n8.x4.shared.b16 {%0,%1,%2,%3}, [%4];"
        : "=r"(r[0]), "=r"(r[1]), "=r"(r[2]), "=r"(r[3]) : "r"(addr));
}

// fp16 mma m16n8k16, fp32 accumulate (in place)
static __device__ __forceinline__ void mma16(float* d, const unsigned* a, unsigned b0, unsigned b1) {
    asm volatile(
        "mma.sync.aligned.m16n8k16.row.col.f32.f16.f16.f32 "
        "{%0,%1,%2,%3},{%4,%5,%6,%7},{%8,%9},{%0,%1,%2,%3};"
        : "+f"(d[0]), "+f"(d[1]), "+f"(d[2]), "+f"(d[3])
        : "r"(a[0]), "r"(a[1]), "r"(a[2]), "r"(a[3]), "r"(b0), "r"(b1));
}

static __device__ __forceinline__ unsigned ld_acq(const unsigned* p) {
    unsigned v;
    asm volatile("ld.global.acquire.gpu.u32 %0, [%1];" : "=r"(v) : "l"(p));
    return v;
}
static __device__ __forceinline__ void red_add_rel(unsigned* p, unsigned v) {
    asm volatile("red.release.gpu.global.add.u32 [%0], %1;" :: "l"(p), "r"(v));
}

// ---------------------------------------------------------------------------
// Init + input conversion kernels (run every replay; cheap)
// ---------------------------------------------------------------------------
__global__ void init_kernel(const float* __restrict__ h0) {
    int i = blockIdx.x * 256 + threadIdx.x;       // 65536 threads == BB*NN
    g_hbuf[0][i] = __float2half_rn(h0[i]);
    if (i < 128 * 8) g_flags[i] = 0u;
}

__global__ void conv_x_kernel(const float* __restrict__ x) {
    size_t i = (size_t)blockIdx.x * 256 + threadIdx.x;   // BB*TT*DD threads
    g_xh[i] = __float2half_rn(x[i]);
}

// g_wxt[gate][n][k] = fp16(Wgate[k][n])
__global__ void conv_w_kernel(
    const float* __restrict__ Wfx, const float* __restrict__ Wix,
    const float* __restrict__ Wox, const float* __restrict__ Wcx)
{
    size_t e = (size_t)blockIdx.x * 256 + threadIdx.x;   // 4*NN*DD threads
    int k    = (int)(e & (DD - 1));
    int n    = (int)((e >> 9) & (NN - 1));
    int gate = (int)(e >> 19);
    const float* W = (gate == 0) ? Wfx : (gate == 1) ? Wix : (gate == 2) ? Wox : Wcx;
    g_wxt[e] = __float2half_rn(W[(size_t)k * NN + n]);
}

// ---------------------------------------------------------------------------
// Phase 1: xp = x @ [Wfx|Wix|Wox|Wcx] + bias  (fp16 m16n8k16, fp32 acc)
// grid (256 m-blocks, 32 n-blocks), 256 threads, BM=BN=128, BK=64 halfs.
// Ring-3 single-sync pipeline, stride-36 rows (conflict-free ldsm).
// ---------------------------------------------------------------------------
#define P1_TSTR  36                       // words per row
#define P1_TILE  (128 * P1_TSTR)          // 4608 words per tile
#define P1_SMEMB (3 * 2 * P1_TILE * 4)    // 110592 bytes (3 slots x (A+B))

__global__ void __launch_bounds__(256, 2) xproj_kernel(
    const float* __restrict__ bf, const float* __restrict__ bi,
    const float* __restrict__ bo, const float* __restrict__ bc)
{
    extern __shared__ unsigned smu[];
    unsigned* AsP = smu;                      // [3][128][36]
    unsigned* BsP = smu + 3 * P1_TILE;        // [3][128][36]

    const int tid  = threadIdx.x;
    const int warp = tid >> 5, lane = tid & 31;
    const int g    = lane >> 2, tig = lane & 3;
    const int wm   = warp >> 1, wn = warp & 1;
    const int M0   = blockIdx.x * 128;
    const int gate = blockIdx.y >> 3;
    const int nc0  = (blockIdx.y & 7) * 128;
    const __half* Wt  = g_wxt + (size_t)gate * NN * DD;
    const float* bias = (gate == 0) ? bf : (gate == 1) ? bi : (gate == 2) ? bo : bc;

    const unsigned sb = smaddr(smu);
    const unsigned aoff = sb + (((wm * 32 + (lane & 15)) * P1_TSTR + (lane >> 4) * 4) << 2);
    const unsigned boff0 = sb + ((3 * P1_TILE +
                     ((wn * 64 + (lane & 7) + ((lane >> 4) & 1) * 8) * P1_TSTR +
                      ((lane >> 3) & 1) * 4)) << 2);

    float acc[2][8][4];
    #pragma unroll
    for (int a = 0; a < 2; a++)
        #pragma unroll
        for (int b = 0; b < 8; b++)
            #pragma unroll
            for (int q = 0; q < 4; q++) acc[a][b][q] = 0.0f;

    auto stage = [&](int c) {
        const int k0 = c * 64;                           // halfs
        const int slot = c % 3;
        unsigned* Ad = AsP + slot * P1_TILE;
        unsigned* Bd = BsP + slot * P1_TILE;
        #pragma unroll
        for (int i = 0; i < 4; i++) {
            int s = tid + 256 * i;                       // 0..1023: 128 rows x 8 segs
            int row = s >> 3, seg = s & 7;
            CP16(smaddr(Ad + row * P1_TSTR + seg * 4),
                 g_xh + (size_t)(M0 + row) * DD + k0 + seg * 8);
            CP16(smaddr(Bd + row * P1_TSTR + seg * 4),
                 Wt + (size_t)(nc0 + row) * DD + k0 + seg * 8);
        }
        CPCOMMIT();
    };

    stage(0);
    for (int c = 0; c < 8; c++) {
        if (c + 1 < 8) { stage(c + 1); cpwait<1>(); }
        else           { cpwait<0>(); }
        __syncthreads();
        const unsigned bufB = (unsigned)((c % 3) * P1_TILE * 4);
        #pragma unroll
        for (int ks2 = 0; ks2 < 4; ks2++) {
            const unsigned kB = bufB + ks2 * 32;         // 8 words = 32 bytes
            unsigned a[2][4];
            ldsm4(a[0], aoff + kB);
            ldsm4(a[1], aoff + kB + 16 * P1_TSTR * 4);
            #pragma unroll
            for (int nfp = 0; nfp < 4; nfp++) {
                unsigned b4[4];
                ldsm4(b4, boff0 + kB + nfp * 16 * P1_TSTR * 4);
                mma16(acc[0][2 * nfp],     a[0], b4[0], b4[1]);
                mma16(acc[1][2 * nfp],     a[1], b4[0], b4[1]);
                mma16(acc[0][2 * nfp + 1], a[0], b4[2], b4[3]);
                mma16(acc[1][2 * nfp + 1], a[1], b4[2], b4[3]);
            }
        }
    }

    #pragma unroll
    for (int mf = 0; mf < 2; mf++) {
        #pragma unroll
        for (int rr = 0; rr < 2; rr++) {
            int m = M0 + wm * 32 + mf * 16 + g + rr * 8;
            int b = m >> 9, t = m & 511;
            size_t base = ((size_t)t * BB + b) * GG + (size_t)blockIdx.y * 128;
            #pragma unroll
            for (int nf = 0; nf < 8; nf++) {
                int col = wn * 64 + nf * 8 + 2 * tig;
                float v0 = acc[mf][nf][rr * 2 + 0] + bias[nc0 + col];
                float v1 = acc[mf][nf][rr * 2 + 1] + bias[nc0 + col + 1];
                *(float2*)&g_xp[base + col] = make_float2(v0, v1);
            }
        }
    }
}

// ---------------------------------------------------------------------------
// Phase 2: persistent LSTM recurrence. 128 CTAs x 256 threads (8 warps).
// fp16 h + fp16 Wh fragments, m16n8k16. 2-row x 4-k warp split, 8 chunks,
// 4-deep ring, two 16-lane parallel producer waits per step.
//
// TWO DECOUPLED HALF-PIPELINES per CTA:
//   half H = warps {H, H+2, H+4, H+6} (rhh = warp&1 = H). GEMM A-rows
//   [32H,+32) AND update rows [32H,+32) both live on exactly these warps
//   (bown = rhh*32 + kq*8 + g). Per-step sync = named barrier (1+H, 128
//   threads); release = per-warp red.add on counter_H (4 adds/step);
//   consumer warp rhh polls only counter_rhh of its producers (>= 4t,
//   monotone: a warp can't pass barrier t+1 until all same-half warps
//   added for step t). Rows [32H,+32) of the h-ring are read only by
//   rhh=H GEMM warps and written only by half-H update warps, so each
//   half's wait->barrier->release chain closes over all 128 CTAs
//   independently; ring-parity and redbuf-parity arguments carry over
//   within each half.
// ---------------------------------------------------------------------------
#define P2_WHU    16384                   // Wh fragment uints: 64 ks x 2 parts x 32 x 4
#define P2_CHW    (32 * 20)               // chunk: 32 rows x 20 words = 640 words
#define P2_RING   (4 * P2_CHW)            // 4-slot ring per warp = 2560 words
#define P2_REDW   (2 * 8 * 1024)          // redbuf: 2 parity x 8 warps x 1024 floats
#define P2_SMEMW  (P2_WHU + 8 * P2_RING + P2_REDW)  // 53248 words
#define P2_SMEMB  (P2_SMEMW * 4)          // 212992 bytes

__global__ void __launch_bounds__(256, 1) lstm_kernel(
    const float* __restrict__ c0,
    const float* __restrict__ Wfh, const float* __restrict__ Wih,
    const float* __restrict__ Woh, const float* __restrict__ Wch,
    const float* __restrict__ wcf, const float* __restrict__ wci,
    const float* __restrict__ wco,
    float* __restrict__ out)
{
    extern __shared__ unsigned smu[];
    unsigned* whfu = smu;                         // fill view
    const uint4* whf4 = (const uint4*)smu;        // [(ks*2+part)*32 + lane]
    unsigned* Aswbase = smu + P2_WHU;             // 8 warp rings
    float* redf = (float*)(smu + P2_WHU + 8 * P2_RING);  // [2][8][1024]

    const int tid  = threadIdx.x;
    const int warp = tid >> 5, lane = tid & 31;
    const int g    = lane >> 2, tig = lane & 3;
    const int cta  = blockIdx.x;
    const int n0   = cta * 8;

    const int rhh = warp & 1;                 // row half (32 rows) AND pipeline id
    const int kq  = warp >> 1;                // k quarter (256 halfs)
    const int rowbase = rhh * 32;
    const int kbase   = kq * 256;

    unsigned* Asw = Aswbase + warp * P2_RING;

    // LDSM A-frag base (bytes) for m-tile mt: rows mt*16 + (lane&15), seg (lane>>4)*4
    const unsigned aaddr0 = smaddr(Asw) + (((lane & 15) * 20 + (lane >> 4) * 4) << 2);

    // --- Prologue: build fp16 Wh fragments in SMEM (resident for all steps)
    for (int e = tid; e < P2_WHU; e += 256) {
        int j     = e & 3;
        int lane_ = (e >> 2) & 31;
        int part  = (e >> 7) & 1;
        int ks    = e >> 8;                    // 0..63
        int gate  = part * 2 + (j >> 1);       // 0=f 1=i 2=o 3=c
        int which = j & 1;                     // b0 / b1
        int tg    = lane_ & 3;
        int col   = n0 + (lane_ >> 2);
        int kb    = ks * 16 + 2 * tg + which * 8;
        const float* Wsel = (gate == 0) ? Wfh : (gate == 1) ? Wih : (gate == 2) ? Woh : Wch;
        __half2 v = __floats2half2_rn(Wsel[(size_t)kb * NN + col],
                                      Wsel[(size_t)(kb + 1) * NN + col]);
        whfu[e] = h2u(v);
    }

    // --- Per-thread update-cell ownership: 1 row x 2 cols
    // bown = rhh*32 + kq*8 + g: update warps of half H == GEMM warps of half H.
    const int bown = rhh * 32 + kq * 8 + g;
    const int nA   = n0 + 2 * tig;
    // Reduction source selectors: sources = warps {rhh + 2j}; within source
    // frag: tile mt_r = kq>>1, row-pair hb_r = kq&1, lane = own lane.
    const int mt_r = kq >> 1;
    const int hb_r = kq & 1;

    float2 cv2 = *(const float2*)&c0[bown * NN + nA];
    float creg[2] = {cv2.x, cv2.y};
    float2 pf2 = *(const float2*)&wcf[nA];
    float2 pi2 = *(const float2*)&wci[nA];
    float2 po2 = *(const float2*)&wco[nA];
    const float pfv[2] = {pf2.x, pf2.y};
    const float piv[2] = {pi2.x, pi2.y};
    const float pov[2] = {po2.x, po2.y};

    __syncthreads();   // whf ready

    // Per-warp producer flag pointers (16 producers per chunk-half, own row-half counter)
    const unsigned* flag_h0 = &g_flags[(32 * kq + (lane & 15)) * 8 + rhh];
    const unsigned* flag_h1 = &g_flags[(32 * kq + 16 + (lane & 15)) * 8 + rhh];

    for (int t = 0; t < TT; t++) {
        const __half* hsrc = g_hbuf[t & 1];
        __half* hdst = g_hbuf[(t + 1) & 1];
        float* redp = redf + (t & 1) * (8 * 1024);

        // Prefetch xp BEFORE any wait (no h dependency)
        const float* xpt = g_xp + (size_t)t * BB * GG;
        float2 xv[4];
        #pragma unroll
        for (int nt = 0; nt < 4; nt++)
            xv[nt] = *(const float2*)&xpt[(size_t)bown * GG + nt * NN + nA];

        float acc[2][4][4] __attribute__((aligned(16)));
        #pragma unroll
        for (int a = 0; a < 2; a++)
            #pragma unroll
            for (int b = 0; b < 4; b++)
                #pragma unroll
                for (int q = 0; q < 4; q++) acc[a][b][q] = 0.0f;

        // Stage chunk c: rows rowbase..+32, k halfs kbase + c*32..+32
        auto stageh = [&](int c) {
            const __half* src = hsrc + (size_t)rowbase * NN + kbase + c * 32;
            unsigned* dst = Asw + (c & 3) * P2_CHW;
            #pragma unroll
            for (int i = 0; i < 4; i++) {
                int s = lane + 32 * i;                // 32 rows x 4 16B-segs
                int row = s >> 2, seg = s & 3;
                CP16(smaddr(dst + row * 20 + seg * 4), src + (size_t)row * NN + seg * 8);
            }
            CPCOMMIT();
        };

        // Chunk-half-0 producers (chunks 0-3): one parallel 16-lane poll
        if (t > 0) {
            const unsigned tgt = (unsigned)(4 * t);
            if (lane < 16) { while (ld_acq(flag_h0) < tgt) { } }
            __syncwarp();
        }
        stageh(0); stageh(1); stageh(2); stageh(3);

        #pragma unroll
        for (int c = 0; c < 8; c++) {
            if (c <= 4)      cpwait<3>();
            else if (c == 5) cpwait<2>();
            else if (c == 6) cpwait<1>();
            else             cpwait<0>();
            __syncwarp();     // cp.async visibility across lanes before collective ldsm
            const unsigned abase = aaddr0 + (unsigned)((c & 3) * P2_CHW * 4);
            #pragma unroll
            for (int ks2 = 0; ks2 < 2; ks2++) {
                const int ks = kq * 16 + c * 2 + ks2;
                const uint4 uA = whf4[(ks * 2 + 0) * 32 + lane];
                const uint4 uB = whf4[(ks * 2 + 1) * 32 + lane];
                #pragma unroll
                for (int mt = 0; mt < 2; mt++) {
                    unsigned a[4];
                    ldsm4(a, abase + (unsigned)(mt * 16 * 20 * 4) + ks2 * 32);
                    mma16(acc[mt][0], a, uA.x, uA.y);   // forget
                    mma16(acc[mt][1], a, uA.z, uA.w);   // input
                    mma16(acc[mt][2], a, uB.x, uB.y);   // output
                    mma16(acc[mt][3], a, uB.z, uB.w);   // cell
                }
            }
            // Chunk-half-1 producers (chunks 4-7): waited once, after chunk 0
            if (c == 0 && t > 0) {
                const unsigned tgt = (unsigned)(4 * t);
                if (lane < 16) { while (ld_acq(flag_h1) < tgt) { } }
                __syncwarp();
            }
            if (c + 4 < 8) stageh(c + 4);
        }

        // --- Cross-warp (4-way, same-half) reduction via parity redbuf
        #pragma unroll
        for (int mt = 0; mt < 2; mt++)
            #pragma unroll
            for (int gt = 0; gt < 4; gt++)
                *(float4*)&redp[warp * 1024 + ((mt * 4 + gt) * 32 + lane) * 4] =
                    *(const float4*)acc[mt][gt];
        // Named barrier: only this half's 4 warps (128 threads)
        asm volatile("bar.sync %0, 128;" :: "r"(1 + rhh) : "memory");

        float fin[4][2];
        #pragma unroll
        for (int gt = 0; gt < 4; gt++) {
            float2 s = make_float2(0.f, 0.f);
            #pragma unroll
            for (int j = 0; j < 4; j++) {
                float2 v = *(const float2*)&redp[(rhh + 2 * j) * 1024 +
                            ((mt_r * 4 + gt) * 32 + lane) * 4 + hb_r * 2];
                s.x += v.x; s.y += v.y;
            }
            fin[gt][0] = s.x; fin[gt][1] = s.y;
        }

        // --- Fused peephole cell update (h ring store first)
        float hv[2];
        #pragma unroll
        for (int q = 0; q < 2; q++) {
            float xf = ((const float*)&xv[0])[q];
            float xi = ((const float*)&xv[1])[q];
            float xo = ((const float*)&xv[2])[q];
            float xc = ((const float*)&xv[3])[q];
            float cp = creg[q];
            float fg = sigf(xf + fin[0][q] + pfv[q] * cp);
            float ig = sigf(xi + fin[1][q] + piv[q] * cp);
            float ct = tanh_fast(xc + fin[3][q]);
            float cn = fg * cp + ig * ct;
            float og = sigf(xo + fin[2][q] + pov[q] * cn);
            float hn = og * tanh_fast(cn);
            creg[q] = cn;
            hv[q] = hn;
        }
        *(__half2*)&hdst[bown * NN + nA] = __floats2half2_rn(hv[0], hv[1]);

        // Per-warp release on this half's counter: syncwarp orders lanes' h
        // stores, then lane0 adds (4 adds/step/half across the 4 warps).
        __syncwarp();
        if (lane == 0) red_add_rel(&g_flags[cta * 8 + rhh], 1u);

        // out[] store off the critical path
        *(float2*)&out[((size_t)bown * TT + t) * NN + nA] = make_float2(hv[0], hv[1]);
    }
}

// ---------------------------------------------------------------------------
// Launch. Input order detected from in_sizes (dict vs signature order).
// ---------------------------------------------------------------------------
extern "C" void kernel_launch(void* const* d_in, const int* in_sizes, int n_in,
                              void* d_out, int out_size) {
    const float* x   = (const float*)d_in[0];
    const float* c0  = (const float*)d_in[1];
    const float* h0  = (const float*)d_in[2];

    const float *Wfx, *bf, *Wix, *bi, *Wox, *bo, *Wcx, *bc;
    const float *Wfh, *Wih, *Woh, *Wch, *wcf, *wci, *wco;

    if (in_sizes[5] == NN * NN) {
        Wfx = (const float*)d_in[3];  bf  = (const float*)d_in[4];  Wfh = (const float*)d_in[5];
        Wix = (const float*)d_in[6];  bi  = (const float*)d_in[7];  Wih = (const float*)d_in[8];
        Wox = (const float*)d_in[9];  bo  = (const float*)d_in[10]; Woh = (const float*)d_in[11];
        Wcx = (const float*)d_in[12]; bc  = (const float*)d_in[13]; Wch = (const float*)d_in[14];
        wcf = (const float*)d_in[15]; wci = (const float*)d_in[16]; wco = (const float*)d_in[17];
    } else {
        Wfx = (const float*)d_in[3];  bf  = (const float*)d_in[4];
        Wix = (const float*)d_in[5];  bi  = (const float*)d_in[6];
        Wox = (const float*)d_in[7];  bo  = (const float*)d_in[8];
        Wcx = (const float*)d_in[9];  bc  = (const float*)d_in[10];
        Wfh = (const float*)d_in[11]; Wih = (const float*)d_in[12];
        Woh = (const float*)d_in[13]; Wch = (const float*)d_in[14];
        wcf = (const float*)d_in[15]; wci = (const float*)d_in[16]; wco = (const float*)d_in[17];
    }
    float* out = (float*)d_out;

    cudaFuncSetAttribute(xproj_kernel, cudaFuncAttributeMaxDynamicSharedMemorySize, P1_SMEMB);
    cudaFuncSetAttribute(lstm_kernel,  cudaFuncAttributeMaxDynamicSharedMemorySize, P2_SMEMB);

    init_kernel<<<256, 256>>>(h0);
    conv_x_kernel<<<(BB * TT * DD) / 256, 256>>>(x);
    conv_w_kernel<<<(4 * NN * DD) / 256, 256>>>(Wfx, Wix, Wox, Wcx);

    dim3 g1(256, 32);
    xproj_kernel<<<g1, 256, P1_SMEMB>>>(bf, bi, bo, bc);

    lstm_kernel<<<128, 256, P2_SMEMB>>>(c0, Wfh, Wih, Woh, Wch, wcf, wci, wco, out);
}